// round 1
// baseline (speedup 1.0000x reference)
#include <cuda_runtime.h>
#include <cstddef>

#define HH 320
#define WW 320
#define CC 64
#define BB 2
#define HW (HH*WW)              // 102400
#define CHW ((size_t)CC*HW)     // 6553600
#define TENSOR_ELEMS (BB*CHW)   // 13107200

#define QT 32
#define ROWP 324                // padded row stride (floats) for smem rows

// Scratch (static device arrays; no allocation allowed)
__device__ float g_M[2*CC*CC];          // M_ud, M_du (64x64 each)
__device__ float g_buf[2][TENSOR_ELEMS]; // buffer_d, buffer_u
__device__ float g_t[2][TENSOR_ELEMS];   // relu(conv1) intermediates

// ---------------------------------------------------------------------------
// Kernel 1: M[a][b] = sum_c Wq[c][a] * Wk[c][b]   (64x64)
// ---------------------------------------------------------------------------
__global__ void kcomputeM(const float* __restrict__ Wq,
                          const float* __restrict__ Wk, int dir) {
    __shared__ float sq[64*64];
    __shared__ float sk[64*64];
    int t = threadIdx.x;
    for (int i = t; i < 4096; i += 256) { sq[i] = Wq[i]; sk[i] = Wk[i]; }
    __syncthreads();
    for (int i = t; i < 4096; i += 256) {
        int a = i >> 6, b = i & 63;
        float s = 0.f;
        #pragma unroll 16
        for (int c = 0; c < 64; c++) s += sq[c*64 + a] * sk[c*64 + b];
        g_M[dir*4096 + i] = s;
    }
}

// ---------------------------------------------------------------------------
// Kernel 2: fused axial attention, both directions, one block per (b,h).
// smem: su[64][ROWP], sd[64][ROWP], sS[QT][ROWP], sr[2048], sM[4096]
// ---------------------------------------------------------------------------
#define ATTN_SMEM ((64*ROWP*2 + QT*ROWP + 2048 + 4096) * 4)

__global__ __launch_bounds__(256)
void kattn(const float* __restrict__ u, const float* __restrict__ d) {
    extern __shared__ float smem[];
    float* su = smem;
    float* sd = su + 64*ROWP;
    float* sS = sd + 64*ROWP;
    float* sr = sS + QT*ROWP;
    float* sM = sr + 2048;

    int tid  = threadIdx.x;
    int lane = tid & 31, warp = tid >> 5;
    int b = blockIdx.x / HH, h = blockIdx.x % HH;
    const float* ubase = u + (size_t)b*CHW + (size_t)h*WW;
    const float* dbase = d + (size_t)b*CHW + (size_t)h*WW;

    for (int i = tid; i < 64*WW; i += 256) {
        int c = i / WW, w = i % WW;
        su[c*ROWP + w] = ubase[(size_t)c*HW + w];
        sd[c*ROWP + w] = dbase[(size_t)c*HW + w];
    }
    __syncthreads();

    for (int dir = 0; dir < 2; dir++) {
        const float* Mg = g_M + dir*4096;
        for (int i = tid; i < 4096; i += 256) sM[i] = Mg[i];
        float* sQ = (dir == 0) ? su : sd;   // query source row
        float* sV = (dir == 0) ? sd : su;   // key/value source row
        float* outg = g_buf[dir] + (size_t)b*CHW + (size_t)h*WW;
        __syncthreads();

        for (int q0 = 0; q0 < WW; q0 += QT) {
            // r[bb][q] = sum_a sQ[a][q0+q] * M[a][bb]
            for (int i = tid; i < 64*QT; i += 256) {
                int bb = i >> 5, q = i & 31;
                float s = 0.f;
                #pragma unroll 8
                for (int a = 0; a < 64; a++)
                    s += sQ[a*ROWP + q0 + q] * sM[a*64 + bb];
                sr[i] = s;
            }
            __syncthreads();

            // scores: warp handles rows q = warp*4..+3 ; lane covers v = lane+32j
            float acc[4][10];
            #pragma unroll
            for (int i = 0; i < 4; i++)
                #pragma unroll
                for (int j = 0; j < 10; j++) acc[i][j] = 0.f;
            for (int bb = 0; bb < 64; bb++) {
                float rv[4];
                #pragma unroll
                for (int i = 0; i < 4; i++) rv[i] = sr[bb*QT + warp*4 + i];
                #pragma unroll
                for (int j = 0; j < 10; j++) {
                    float dv = sV[bb*ROWP + lane + 32*j];
                    #pragma unroll
                    for (int i = 0; i < 4; i++) acc[i][j] += rv[i]*dv;
                }
            }
            // exact softmax per row (row lives in one warp)
            #pragma unroll
            for (int i = 0; i < 4; i++) {
                float m = acc[i][0];
                #pragma unroll
                for (int j = 1; j < 10; j++) m = fmaxf(m, acc[i][j]);
                #pragma unroll
                for (int o = 16; o > 0; o >>= 1) m = fmaxf(m, __shfl_xor_sync(~0u, m, o));
                float s = 0.f;
                #pragma unroll
                for (int j = 0; j < 10; j++) { acc[i][j] = __expf(acc[i][j] - m); s += acc[i][j]; }
                #pragma unroll
                for (int o = 16; o > 0; o >>= 1) s += __shfl_xor_sync(~0u, s, o);
                float inv = 1.f / s;
                #pragma unroll
                for (int j = 0; j < 10; j++)
                    sS[(warp*4 + i)*ROWP + lane + 32*j] = acc[i][j]*inv;
            }
            __syncthreads();

            // attend: out[c][q] = sum_v P[q][v] * sV[c][v]; split v in 2 halves
            {
                int half = tid >> 7;
                int t2 = tid & 127;
                int qg = t2 & 7;       // q = qg + 8*iq  (conflict-free stride)
                int cg = t2 >> 3;      // c = cg + 16*ic
                float oacc[4][4];
                #pragma unroll
                for (int ic = 0; ic < 4; ic++)
                    #pragma unroll
                    for (int iq = 0; iq < 4; iq++) oacc[ic][iq] = 0.f;
                int vbeg = half*160;
                for (int v = vbeg; v < vbeg + 160; v += 4) {
                    float4 pv[4], vv[4];
                    #pragma unroll
                    for (int iq = 0; iq < 4; iq++)
                        pv[iq] = *(const float4*)&sS[(qg + 8*iq)*ROWP + v];
                    #pragma unroll
                    for (int ic = 0; ic < 4; ic++)
                        vv[ic] = *(const float4*)&sV[(cg + 16*ic)*ROWP + v];
                    #pragma unroll
                    for (int ic = 0; ic < 4; ic++)
                        #pragma unroll
                        for (int iq = 0; iq < 4; iq++)
                            oacc[ic][iq] += vv[ic].x*pv[iq].x + vv[ic].y*pv[iq].y
                                          + vv[ic].z*pv[iq].z + vv[ic].w*pv[iq].w;
                }
                if (half == 0) {
                    #pragma unroll
                    for (int ic = 0; ic < 4; ic++)
                        #pragma unroll
                        for (int iq = 0; iq < 4; iq++)
                            sr[(cg + 16*ic)*QT + (qg + 8*iq)] = oacc[ic][iq];
                }
                __syncthreads();
                if (half == 1) {
                    #pragma unroll
                    for (int ic = 0; ic < 4; ic++)
                        #pragma unroll
                        for (int iq = 0; iq < 4; iq++)
                            sr[(cg + 16*ic)*QT + (qg + 8*iq)] += oacc[ic][iq];
                }
                __syncthreads();
            }
            // write buffer tile
            for (int i = tid; i < 64*QT; i += 256) {
                int c = i >> 5, q = i & 31;
                outg[(size_t)c*HW + q0 + q] = sr[i];
            }
            __syncthreads();
        }
        __syncthreads();
    }
}

// ---------------------------------------------------------------------------
// Kernel 3: direct 3x3 conv, SAME padding, optional concat input + relu.
// Block: 64 out-ch x (32x x 8y) tile; warp=o-group, lane=x; thread: 8o x 8y.
// ---------------------------------------------------------------------------
#define CONV_SMEM ((16*10*36 + 16*64*12) * 4)

template<int CIN, bool RELU>
__global__ __launch_bounds__(256)
void kconv(const float* __restrict__ in1, const float* __restrict__ in2,
           const float* __restrict__ Wt, float* __restrict__ out) {
    extern __shared__ float csm[];
    float* sin_ = csm;              // [16][10][36]
    float* sw_  = csm + 16*10*36;   // [16][64][12] (9 taps padded to 12)

    int tid  = threadIdx.x;
    int lane = tid & 31, warp = tid >> 5;
    int x0 = blockIdx.x * 32;
    int y0 = blockIdx.y * 8;
    int b  = blockIdx.z;

    float acc[8][8];
    #pragma unroll
    for (int i = 0; i < 8; i++)
        #pragma unroll
        for (int j = 0; j < 8; j++) acc[i][j] = 0.f;

    for (int cb = 0; cb < CIN; cb += 16) {
        // stage input tile (zero-padded borders)
        for (int i = tid; i < 16*10*36; i += 256) {
            int ci  = i / 360;
            int rem = i % 360;
            int ry  = rem / 36;
            int k   = rem % 36;
            int gy = y0 + ry - 1;
            int gx = x0 + k - 1;
            float v = 0.f;
            if (k < 34 && gy >= 0 && gy < HH && gx >= 0 && gx < WW) {
                int cglob = cb + ci;
                const float* src;
                if (CIN == 128 && cglob >= 64)
                    src = in2 + (size_t)b*CHW + (size_t)(cglob - 64)*HW;
                else
                    src = in1 + (size_t)b*CHW + (size_t)cglob*HW;
                v = src[gy*WW + gx];
            }
            sin_[i] = v;
        }
        // stage weights
        for (int i = tid; i < 16*64*9; i += 256) {
            int ci  = i / 576;
            int rem = i % 576;
            int o   = rem / 9;
            int t   = rem % 9;
            sw_[(ci*64 + o)*12 + t] = Wt[(size_t)o*(CIN*9) + (size_t)(cb + ci)*9 + t];
        }
        __syncthreads();

        #pragma unroll 1
        for (int ci = 0; ci < 16; ci++) {
            float v[3][10];
            #pragma unroll
            for (int ry = 0; ry < 10; ry++)
                #pragma unroll
                for (int dx = 0; dx < 3; dx++)
                    v[dx][ry] = sin_[ci*360 + ry*36 + lane + dx];
            #pragma unroll
            for (int o8 = 0; o8 < 8; o8++) {
                const float4* wp = (const float4*)&sw_[(ci*64 + warp*8 + o8)*12];
                float4 w0 = wp[0], w1 = wp[1], w2 = wp[2];
                #pragma unroll
                for (int py = 0; py < 8; py++) {
                    float s = acc[o8][py];
                    s += w0.x * v[0][py+0];
                    s += w0.y * v[1][py+0];
                    s += w0.z * v[2][py+0];
                    s += w0.w * v[0][py+1];
                    s += w1.x * v[1][py+1];
                    s += w1.y * v[2][py+1];
                    s += w1.z * v[0][py+2];
                    s += w1.w * v[1][py+2];
                    s += w2.x * v[2][py+2];
                    acc[o8][py] = s;
                }
            }
        }
        __syncthreads();
    }

    #pragma unroll
    for (int o8 = 0; o8 < 8; o8++) {
        int o = warp*8 + o8;
        float* dst = out + (size_t)b*CHW + (size_t)o*HW + (size_t)y0*WW + x0 + lane;
        #pragma unroll
        for (int py = 0; py < 8; py++) {
            float val = acc[o8][py];
            if (RELU) val = fmaxf(val, 0.f);
            dst[(size_t)py*WW] = val;
        }
    }
}

// ---------------------------------------------------------------------------
extern "C" void kernel_launch(void* const* d_in, const int* in_sizes, int n_in,
                              void* d_out, int out_size) {
    const float* u   = (const float*)d_in[0];
    const float* d   = (const float*)d_in[1];
    const float* Wu1 = (const float*)d_in[2];
    const float* Wu2 = (const float*)d_in[3];
    const float* Wd1 = (const float*)d_in[4];
    const float* Wd2 = (const float*)d_in[5];
    const float* W1a = (const float*)d_in[6];
    const float* W1b = (const float*)d_in[7];
    const float* W2a = (const float*)d_in[8];
    const float* W2b = (const float*)d_in[9];
    float* out = (float*)d_out;

    cudaFuncSetAttribute(kattn, cudaFuncAttributeMaxDynamicSharedMemorySize, ATTN_SMEM);
    cudaFuncSetAttribute(kconv<128, true>,  cudaFuncAttributeMaxDynamicSharedMemorySize, CONV_SMEM);
    cudaFuncSetAttribute(kconv<64, false>,  cudaFuncAttributeMaxDynamicSharedMemorySize, CONV_SMEM);

    float *pbuf0, *pbuf1, *pt0, *pt1;
    cudaGetSymbolAddress((void**)&pbuf0, g_buf);
    pbuf1 = pbuf0 + TENSOR_ELEMS;
    cudaGetSymbolAddress((void**)&pt0, g_t);
    pt1 = pt0 + TENSOR_ELEMS;

    // 1. fold 1x1 projections into 64x64 bilinear matrices
    kcomputeM<<<1, 256>>>(Wu1, Wd2, 0);   // M_ud
    kcomputeM<<<1, 256>>>(Wd1, Wu2, 1);   // M_du

    // 2. fused cross attention (both directions) -> g_buf
    kattn<<<BB*HH, 256, ATTN_SMEM>>>(u, d);

    // 3. conv1 + relu on concat(stream, buffer)
    dim3 grid(WW/32, HH/8, BB);
    kconv<128, true><<<grid, 256, CONV_SMEM>>>(u, pbuf0, W1a, pt0);
    kconv<128, true><<<grid, 256, CONV_SMEM>>>(d, pbuf1, W2a, pt1);

    // 4. conv2 -> outputs
    kconv<64, false><<<grid, 256, CONV_SMEM>>>(pt0, nullptr, W1b, out);
    kconv<64, false><<<grid, 256, CONV_SMEM>>>(pt1, nullptr, W2b, out + TENSOR_ELEMS);
}